// round 15
// baseline (speedup 1.0000x reference)
#include <cuda_runtime.h>
#include <cuda_fp16.h>
#include <mma.h>
#include <cstdint>

using namespace nvcuda;

#define D 128
#define MAXN 100000
#define MAXNP 100096            // MAXN rounded up to 128 (predicate-free GEMM tiles)
#define MAXE 1600000
#define PADE 136                // smem row pitch in fp16 elements (272 B, 16B-aligned)

// ---------------- device scratch (static globals: allocation-free) ----------------
__device__ float  g_hist[3][MAXNP * D];     // hist[1..3] fp32 (residual / normalize path)
__device__ __half g_Hh[2][4][MAXNP * D];    // double-buffered product table (bank = layer&1)
__device__ __half g_xF[MAXNP * D];          // x in fp16 (GEMM A for hist[0])
__device__ __half g_histF[3][MAXNP * D];    // hist[1..3] in fp16 (GEMM A)
__device__ __half g_WtF[4 * D * D];         // Wt[m][n][k] = W[m][k][n], fp16
__device__ int   g_rowStart[MAXN + 1];
__device__ int   g_blockSums[256];
__device__ int   g_degS[4 * MAXN];
__device__ int   g_degD[4 * MAXN];
__device__ int   g_cursorHop[4 * MAXN];
__device__ int2  g_sortedE[MAXE];           // {src | (attr<<20), __float_as_int(coef)}

// ---------------- preprocessing ----------------
__global__ void zero_kernel(int N) {
    int i = blockIdx.x * blockDim.x + threadIdx.x;
    if (i < 4 * N) { g_degS[i] = 0; g_degD[i] = 0; g_cursorHop[i] = 0; }
}

__global__ void hist_kernel(const int* __restrict__ ei, const int* __restrict__ attr, int N, int E) {
    int e = blockIdx.x * blockDim.x + threadIdx.x;
    if (e >= E) return;
    int s = ei[e], d = ei[E + e], a = attr[e];
    atomicAdd(&g_degS[(a - 1) * N + s], 1);
    atomicAdd(&g_degD[(a - 1) * N + d], 1);
}

__global__ void scan1_kernel(int N) {
    __shared__ int sh[1024];
    int t = threadIdx.x;
    int i = blockIdx.x * 1024 + t;
    int v = 0;
    if (i < N) {
        #pragma unroll
        for (int h = 0; h < 4; h++) v += g_degD[h * N + i];
    }
    sh[t] = v;
    __syncthreads();
    for (int off = 1; off < 1024; off <<= 1) {
        int x = (t >= off) ? sh[t - off] : 0;
        __syncthreads();
        sh[t] += x;
        __syncthreads();
    }
    if (i < N) g_rowStart[i] = sh[t] - v;     // exclusive within block
    if (t == 1023) g_blockSums[blockIdx.x] = sh[1023];
}

__global__ void scan2_kernel(int nb) {
    int run = 0;
    for (int b = 0; b < nb; b++) { int x = g_blockSums[b]; g_blockSums[b] = run; run += x; }
}

// bucket edges by (dst, hop): within each dst's range, hops appear in ascending order
__global__ void scatter_kernel(const int* __restrict__ ei, const int* __restrict__ attr, int N, int E) {
    int e = blockIdx.x * blockDim.x + threadIdx.x;
    if (e >= E) return;
    int s = ei[e], d = ei[E + e], a = attr[e];
    int prefix = 0;
    for (int j = 0; j < a - 1; j++) prefix += g_degD[j * N + d];
    int pos = g_rowStart[d] + g_blockSums[d >> 10] + prefix +
              atomicAdd(&g_cursorHop[(a - 1) * N + d], 1);
    float c = rsqrtf((float)g_degS[(a - 1) * N + s]) * rsqrtf((float)g_degD[(a - 1) * N + d]);
    g_sortedE[pos] = make_int2(s | (a << 20), __float_as_int(c));
}

// x -> fp16
__global__ void xconv_kernel(const float* __restrict__ x, int n) {
    int i = blockIdx.x * blockDim.x + threadIdx.x;
    if (i < n) g_xF[i] = __float2half(x[i]);
}

// transpose W -> fp16: Wt[m][n][k] = W[m][k][n]
__global__ void wconv_kernel(const float* __restrict__ W) {
    int o = blockIdx.x * blockDim.x + threadIdx.x;
    if (o >= 4 * D * D) return;
    int m = o >> 14, n = (o >> 7) & 127, k = o & 127;
    g_WtF[o] = __float2half(W[m * D * D + k * D + n]);
}

// ---------------- GEMM body (R10 form: fp32 acc + smem stage + coalesced fp16 stores) ----
#define TILE_E (128 * PADE)
#define GEMM_SMEM (2 * TILE_E * 2)    // 69,632 B
#define STP 136                        // fp32 stage pitch (exact smem reuse)

__device__ __forceinline__ void gemm_body(int rowBase, int hi_idx, int by, int wbank) {
    extern __shared__ __align__(16) __half sm[];
    __half* Ah = sm;
    __half* Bh = sm + TILE_E;
    float* stage = (float*)sm;           // 128 x STP floats = 69,632 B (exact reuse)

    int tid = threadIdx.x, wid = tid >> 5;
    const __half* Asrc = (hi_idx == 0) ? g_xF : g_histF[hi_idx - 1];
    const __half* Bsrc = g_WtF + by * D * D;
    __half* C = g_Hh[wbank][by];

    #pragma unroll
    for (int i = 0; i < 8; i++) {
        int c = tid + i * 256;          // 0..2047
        int r = c >> 4, cc = c & 15;
        int de = r * PADE + cc * 8;
        *(uint4*)(Ah + de) = *(const uint4*)(Asrc + (long)(rowBase + r) * D + cc * 8);
        *(uint4*)(Bh + de) = *(const uint4*)(Bsrc + r * D + cc * 8);
    }
    __syncthreads();

    int m0 = (wid & 3) * 32, n0 = (wid >> 2) * 64;

    wmma::fragment<wmma::accumulator, 16, 16, 16, float> acc[2][4];
    #pragma unroll
    for (int mi = 0; mi < 2; mi++)
        #pragma unroll
        for (int ni = 0; ni < 4; ni++)
            wmma::fill_fragment(acc[mi][ni], 0.0f);

    #pragma unroll
    for (int ks = 0; ks < 8; ks++) {
        wmma::fragment<wmma::matrix_a, 16, 16, 16, __half, wmma::row_major> fa[2];
        #pragma unroll
        for (int mi = 0; mi < 2; mi++)
            wmma::load_matrix_sync(fa[mi], Ah + (m0 + mi * 16) * PADE + ks * 16, PADE);
        wmma::fragment<wmma::matrix_b, 16, 16, 16, __half, wmma::col_major> fb;
        #pragma unroll
        for (int ni = 0; ni < 4; ni++) {
            wmma::load_matrix_sync(fb, Bh + (n0 + ni * 16) * PADE + ks * 16, PADE);
            wmma::mma_sync(acc[0][ni], fa[0], fb, acc[0][ni]);
            wmma::mma_sync(acc[1][ni], fa[1], fb, acc[1][ni]);
        }
    }

    __syncthreads();
    #pragma unroll
    for (int mi = 0; mi < 2; mi++)
        #pragma unroll
        for (int ni = 0; ni < 4; ni++)
            wmma::store_matrix_sync(stage + (m0 + mi * 16) * STP + n0 + ni * 16,
                                    acc[mi][ni], STP, wmma::mem_row_major);
    __syncthreads();

    #pragma unroll
    for (int i = 0; i < 8; i++) {
        int c = tid + i * 256;
        int r = c >> 4, cc = c & 15;
        const float* sp = stage + r * STP + cc * 8;
        float4 f0 = *(const float4*)(sp);
        float4 f1 = *(const float4*)(sp + 4);
        __half2 h0 = __floats2half2_rn(f0.x, f0.y);
        __half2 h1 = __floats2half2_rn(f0.z, f0.w);
        __half2 h2 = __floats2half2_rn(f1.x, f1.y);
        __half2 h3 = __floats2half2_rn(f1.z, f1.w);
        uint4 o;
        o.x = *(uint32_t*)&h0; o.y = *(uint32_t*)&h1;
        o.z = *(uint32_t*)&h2; o.w = *(uint32_t*)&h3;
        *(uint4*)(C + (long)(rowBase + r) * D + cc * 8) = o;
    }
}

// ---------------- agg body (R10 form: flat loop, unroll-2, fp32 acc) ----------------
__device__ __forceinline__ void agg_body(int gw, const float* __restrict__ x,
                                         float* __restrict__ out,
                                         const float* __restrict__ nu, int t, int N,
                                         int rbank) {
    int lane = threadIdx.x & 31;
    if (gw >= N) return;

    const float* hin = (t == 0) ? x : g_hist[t - 1];
    float* hout = (t == 3) ? out : g_hist[t];
    const __half* Hb0 = &g_Hh[rbank][0][0];
    const long pstride = (long)MAXNP * D;

    float nuv[4];
    #pragma unroll
    for (int k = 0; k < 4; k++) nuv[k] = nu[k * 4 + t];

    int eBeg = g_rowStart[gw] + g_blockSums[gw >> 10];
    int cnt = 0;
    #pragma unroll
    for (int h = 0; h < 4; h++) if (h <= t) cnt += g_degD[h * N + gw];
    int eEnd = eBeg + cnt;

    float4 acc0 = make_float4(0.f, 0.f, 0.f, 0.f);
    float4 acc1 = make_float4(0.f, 0.f, 0.f, 0.f);
    int e = eBeg;
    for (; e + 2 <= eEnd; e += 2) {
        int2 p0 = g_sortedE[e];
        int2 p1 = g_sortedE[e + 1];
        int k0 = p0.x >> 20, k1 = p1.x >> 20;
        uint2 hv0 = *(const uint2*)(Hb0 + (k0 - 1) * pstride + (long)(p0.x & 0xFFFFF) * D + lane * 4);
        uint2 hv1 = *(const uint2*)(Hb0 + (k1 - 1) * pstride + (long)(p1.x & 0xFFFFF) * D + lane * 4);
        float s0 = __int_as_float(p0.y) * nuv[k0 - 1];
        float s1 = __int_as_float(p1.y) * nuv[k1 - 1];
        float2 f01 = __half22float2(*(__half2*)&hv0.x);
        float2 f23 = __half22float2(*(__half2*)&hv0.y);
        float2 g01 = __half22float2(*(__half2*)&hv1.x);
        float2 g23 = __half22float2(*(__half2*)&hv1.y);
        acc0.x = fmaf(s0, f01.x, acc0.x); acc0.y = fmaf(s0, f01.y, acc0.y);
        acc0.z = fmaf(s0, f23.x, acc0.z); acc0.w = fmaf(s0, f23.y, acc0.w);
        acc1.x = fmaf(s1, g01.x, acc1.x); acc1.y = fmaf(s1, g01.y, acc1.y);
        acc1.z = fmaf(s1, g23.x, acc1.z); acc1.w = fmaf(s1, g23.y, acc1.w);
    }
    if (e < eEnd) {
        int2 p0 = g_sortedE[e];
        int k0 = p0.x >> 20;
        uint2 hv0 = *(const uint2*)(Hb0 + (k0 - 1) * pstride + (long)(p0.x & 0xFFFFF) * D + lane * 4);
        float s0 = __int_as_float(p0.y) * nuv[k0 - 1];
        float2 f01 = __half22float2(*(__half2*)&hv0.x);
        float2 f23 = __half22float2(*(__half2*)&hv0.y);
        acc0.x = fmaf(s0, f01.x, acc0.x); acc0.y = fmaf(s0, f01.y, acc0.y);
        acc0.z = fmaf(s0, f23.x, acc0.z); acc0.w = fmaf(s0, f23.y, acc0.w);
    }
    float4 acc;
    acc.x = acc0.x + acc1.x; acc.y = acc0.y + acc1.y;
    acc.z = acc0.z + acc1.z; acc.w = acc0.w + acc1.w;

    float4 xin = *(const float4*)(hin + (long)gw * D + lane * 4);
    float4 v;
    v.x = xin.x + fmaxf(acc.x, 0.f);
    v.y = xin.y + fmaxf(acc.y, 0.f);
    v.z = xin.z + fmaxf(acc.z, 0.f);
    v.w = xin.w + fmaxf(acc.w, 0.f);

    float ss = v.x * v.x + v.y * v.y + v.z * v.z + v.w * v.w;
    #pragma unroll
    for (int o = 16; o; o >>= 1) ss += __shfl_xor_sync(0xffffffffu, ss, o);
    float inv = 1.0f / fmaxf(sqrtf(ss), 1e-12f);
    v.x *= inv; v.y *= inv; v.z *= inv; v.w *= inv;

    *(float4*)(hout + (long)gw * D + lane * 4) = v;

    if (t < 3) {   // fp16 copy for next layer's GEMM A
        __half2 h0 = __floats2half2_rn(v.x, v.y);
        __half2 h1 = __floats2half2_rn(v.z, v.w);
        uint2 o;
        o.x = *(uint32_t*)&h0; o.y = *(uint32_t*)&h1;
        *(uint2*)(g_histF[t] + (long)gw * D + lane * 4) = o;
    }
}

// ---------------- standalone kernels ----------------
__global__ __launch_bounds__(256) void gemm_kernel(int hi_idx, int by, int wbank) {
    gemm_body(blockIdx.x * 128, hi_idx, by, wbank);
}

__global__ void agg_kernel(const float* __restrict__ x, float* __restrict__ out,
                           const float* __restrict__ nu, int t, int N, int rbank) {
    agg_body((blockIdx.x * blockDim.x + threadIdx.x) >> 5, x, out, nu, t, N, rbank);
}

// ---------------- fused kernel: agg(t) blocks + independent layer-(t+1) gemm blocks ----
// gemm blocks interleaved every Pd-th block so both populations coexist on the chip.
// products p0..p2: (by<<4)|hi_idx, -1 = unused. gemms write bank wbank = !(t&1).
__global__ __launch_bounds__(256) void fused_kernel(const float* __restrict__ x,
                                                    float* __restrict__ out,
                                                    const float* __restrict__ nu,
                                                    int t, int N,
                                                    int p0, int p1, int p2,
                                                    int Pd, int gemmB, int gx) {
    int b = blockIdx.x;
    int q = b / Pd;
    if (b % Pd == 0 && q < gemmB) {
        int pi = q / gx, rb = (q % gx) * 128;
        int code = (pi == 0) ? p0 : (pi == 1) ? p1 : p2;
        gemm_body(rb, code & 15, code >> 4, (~t) & 1);
    } else {
        int aggIdx = b - min((b + Pd - 1) / Pd, gemmB);
        agg_body(aggIdx * 8 + (threadIdx.x >> 5), x, out, nu, t, N, t & 1);
    }
}

// ---------------- launch ----------------
extern "C" void kernel_launch(void* const* d_in, const int* in_sizes, int n_in,
                              void* d_out, int out_size) {
    const float* x    = (const float*)d_in[0];
    const int*   ei   = (const int*)d_in[1];   // [2,E]: src then dst
    const int*   attr = (const int*)d_in[2];
    const float* W    = (const float*)d_in[3]; // [4,128,128]
    const float* nu   = (const float*)d_in[4]; // [4,4]

    int N = in_sizes[0] / D;
    int E = in_sizes[2];

    cudaFuncSetAttribute(gemm_kernel, cudaFuncAttributeMaxDynamicSharedMemorySize, GEMM_SMEM);
    cudaFuncSetAttribute(fused_kernel, cudaFuncAttributeMaxDynamicSharedMemorySize, GEMM_SMEM);

    const int thr = 256;
    int gx = (N + 127) / 128;
    int aggBlocks = (N * 32 + thr - 1) / thr;
    float* out = (float*)d_out;

    xconv_kernel<<<(N * D + thr - 1) / thr, thr>>>(x, N * D);
    wconv_kernel<<<(4 * D * D + thr - 1) / thr, thr>>>(W);
    zero_kernel<<<(4 * N + thr - 1) / thr, thr>>>(N);
    gemm_kernel<<<gx, 256, GEMM_SMEM>>>(0, 0, 0);            // P(0,0): x@W0 -> bank0
    hist_kernel<<<(E + thr - 1) / thr, thr>>>(ei, attr, N, E);
    int nb = (N + 1023) / 1024;
    scan1_kernel<<<nb, 1024>>>(N);
    scan2_kernel<<<1, 1>>>(nb);
    scatter_kernel<<<(E + thr - 1) / thr, thr>>>(ei, attr, N, E);

    // F(t) product lists: (by<<4)|hi_idx for layer t+1, by>=1 (hi_idx = t+1-by)
    const int plist[3][3] = {
        { (1 << 4) | 0, -1,           -1           },   // F0: P(1,1)=x@W1
        { (1 << 4) | 1, (2 << 4) | 0, -1           },   // F1: P(2,1)=h0@W1, P(2,2)=x@W2
        { (1 << 4) | 2, (2 << 4) | 1, (3 << 4) | 0 },   // F2: P(3,1)=h1@W1, P(3,2)=h0@W2, P(3,3)=x@W3
    };
    const int ng[3] = {1, 2, 3};

    for (int t = 0; t < 3; t++) {
        int gemmB = ng[t] * gx;
        int total = aggBlocks + gemmB;
        int Pd = total / gemmB;
        fused_kernel<<<total, 256, GEMM_SMEM>>>(x, out, nu, t, N,
                                                plist[t][0], plist[t][1], plist[t][2],
                                                Pd, gemmB, gx);
        // P(t+1, 0) = histF[t] @ W0 -> bank (t+1)&1
        gemm_kernel<<<gx, 256, GEMM_SMEM>>>(t + 1, 0, (t + 1) & 1);
    }
    agg_kernel<<<aggBlocks, thr>>>(x, out, nu, 3, N, 1);     // full-occupancy final agg
}

// round 16
// speedup vs baseline: 1.8661x; 1.8661x over previous
#include <cuda_runtime.h>
#include <cuda_fp16.h>
#include <mma.h>
#include <cstdint>

using namespace nvcuda;

#define D 128
#define MAXN 100000
#define MAXNP 100096            // MAXN rounded up to 128 (predicate-free GEMM tiles)
#define MAXE 1600000
#define PADE 136                // smem row pitch in fp16 elements (272 B, 16B-aligned)

// ---------------- device scratch (static globals: allocation-free) ----------------
__device__ float  g_hist[3][MAXNP * D];   // hist[1..3] fp32 (residual / normalize path)
__device__ __half g_Hh[4][MAXNP * D];     // H_k = hist[t+1-k] @ W[k-1], fp16 (JIT per layer)
__device__ __half g_xF[MAXNP * D];        // x in fp16 (GEMM A for hist[0])
__device__ __half g_histF[3][MAXNP * D];  // hist[1..3] in fp16 (GEMM A)
__device__ __half g_WtF[4 * D * D];       // Wt[m][n][k] = W[m][k][n], fp16
__device__ int   g_rowStart[MAXN + 1];
__device__ int   g_blockSums[256];
__device__ int   g_degS[4 * MAXN];
__device__ int   g_degD[4 * MAXN];
__device__ int   g_cursorHop[4 * MAXN];
__device__ int2  g_sortedE[MAXE];         // {src | (attr<<20), __float_as_int(coef)}

// ---------------- preprocessing ----------------
__global__ void zero_kernel(int N) {
    int i = blockIdx.x * blockDim.x + threadIdx.x;
    if (i < 4 * N) { g_degS[i] = 0; g_degD[i] = 0; g_cursorHop[i] = 0; }
}

__global__ void hist_kernel(const int* __restrict__ ei, const int* __restrict__ attr, int N, int E) {
    int e = blockIdx.x * blockDim.x + threadIdx.x;
    if (e >= E) return;
    int s = ei[e], d = ei[E + e], a = attr[e];
    atomicAdd(&g_degS[(a - 1) * N + s], 1);
    atomicAdd(&g_degD[(a - 1) * N + d], 1);
}

__global__ void scan1_kernel(int N) {
    __shared__ int sh[1024];
    int t = threadIdx.x;
    int i = blockIdx.x * 1024 + t;
    int v = 0;
    if (i < N) {
        #pragma unroll
        for (int h = 0; h < 4; h++) v += g_degD[h * N + i];
    }
    sh[t] = v;
    __syncthreads();
    for (int off = 1; off < 1024; off <<= 1) {
        int x = (t >= off) ? sh[t - off] : 0;
        __syncthreads();
        sh[t] += x;
        __syncthreads();
    }
    if (i < N) g_rowStart[i] = sh[t] - v;     // exclusive within block
    if (t == 1023) g_blockSums[blockIdx.x] = sh[1023];
}

// parallel exclusive scan of block sums (nb <= 128), replaces serial scan2
__global__ void scan2_kernel(int nb) {
    __shared__ int sh[128];
    int t = threadIdx.x;
    int v = (t < nb) ? g_blockSums[t] : 0;
    sh[t] = v;
    __syncthreads();
    #pragma unroll
    for (int off = 1; off < 128; off <<= 1) {
        int x = (t >= off) ? sh[t - off] : 0;
        __syncthreads();
        sh[t] += x;
        __syncthreads();
    }
    if (t < nb) g_blockSums[t] = sh[t] - v;   // exclusive
}

// bucket edges by (dst, hop): within each dst's range, hops appear in ascending order
__global__ void scatter_kernel(const int* __restrict__ ei, const int* __restrict__ attr, int N, int E) {
    int e = blockIdx.x * blockDim.x + threadIdx.x;
    if (e >= E) return;
    int s = ei[e], d = ei[E + e], a = attr[e];
    int prefix = 0;
    for (int j = 0; j < a - 1; j++) prefix += g_degD[j * N + d];
    int pos = g_rowStart[d] + g_blockSums[d >> 10] + prefix +
              atomicAdd(&g_cursorHop[(a - 1) * N + d], 1);
    float c = rsqrtf((float)g_degS[(a - 1) * N + s]) * rsqrtf((float)g_degD[(a - 1) * N + d]);
    g_sortedE[pos] = make_int2(s | (a << 20), __float_as_int(c));
}

// fused conversions: x -> fp16, and W transpose -> fp16 (Wt[m][n][k] = W[m][k][n])
__global__ void conv_kernel(const float* __restrict__ x, const float* __restrict__ W, int n) {
    int i = blockIdx.x * blockDim.x + threadIdx.x;
    if (i < n) g_xF[i] = __float2half(x[i]);
    if (i < 4 * D * D) {
        int m = i >> 14, nn = (i >> 7) & 127, k = i & 127;
        g_WtF[i] = __float2half(W[m * D * D + k * D + nn]);
    }
}

// ---------------- wmma GEMM (JIT per layer): g_Hh[by] = A(by,t) @ W[by] ----------------
// R10 form: fp32 accumulators + smem stage + coalesced fp16 stores (best measured).
#define TILE_E (128 * PADE)
#define GEMM_SMEM (2 * TILE_E * 2)    // 69,632 B
#define STP 136                        // fp32 stage pitch (exact smem reuse)

__global__ __launch_bounds__(256) void gemm_wmma_kernel(int t) {
    extern __shared__ __align__(16) __half sm[];
    __half* Ah = sm;
    __half* Bh = sm + TILE_E;
    float* stage = (float*)sm;           // 128 x STP floats = 69,632 B (exact reuse)

    int tid = threadIdx.x, wid = tid >> 5;
    int by = blockIdx.y;           // k-1
    int hi_idx = t - by;           // hist index feeding this product
    const __half* Asrc = (hi_idx == 0) ? g_xF : g_histF[hi_idx - 1];
    const __half* Bsrc = g_WtF + by * D * D;
    __half* C = g_Hh[by];
    int rowBase = blockIdx.x * 128;      // padded arrays: tiles fully in-bounds

    #pragma unroll
    for (int i = 0; i < 8; i++) {
        int c = tid + i * 256;          // 0..2047
        int r = c >> 4, cc = c & 15;
        int de = r * PADE + cc * 8;
        *(uint4*)(Ah + de) = *(const uint4*)(Asrc + (rowBase + r) * D + cc * 8);
        *(uint4*)(Bh + de) = *(const uint4*)(Bsrc + r * D + cc * 8);
    }
    __syncthreads();

    int m0 = (wid & 3) * 32, n0 = (wid >> 2) * 64;

    wmma::fragment<wmma::accumulator, 16, 16, 16, float> acc[2][4];
    #pragma unroll
    for (int mi = 0; mi < 2; mi++)
        #pragma unroll
        for (int ni = 0; ni < 4; ni++)
            wmma::fill_fragment(acc[mi][ni], 0.0f);

    #pragma unroll
    for (int ks = 0; ks < 8; ks++) {
        wmma::fragment<wmma::matrix_a, 16, 16, 16, __half, wmma::row_major> fa[2];
        #pragma unroll
        for (int mi = 0; mi < 2; mi++)
            wmma::load_matrix_sync(fa[mi], Ah + (m0 + mi * 16) * PADE + ks * 16, PADE);
        wmma::fragment<wmma::matrix_b, 16, 16, 16, __half, wmma::col_major> fb;
        #pragma unroll
        for (int ni = 0; ni < 4; ni++) {
            wmma::load_matrix_sync(fb, Bh + (n0 + ni * 16) * PADE + ks * 16, PADE);
            wmma::mma_sync(acc[0][ni], fa[0], fb, acc[0][ni]);
            wmma::mma_sync(acc[1][ni], fa[1], fb, acc[1][ni]);
        }
    }

    __syncthreads();
    #pragma unroll
    for (int mi = 0; mi < 2; mi++)
        #pragma unroll
        for (int ni = 0; ni < 4; ni++)
            wmma::store_matrix_sync(stage + (m0 + mi * 16) * STP + n0 + ni * 16,
                                    acc[mi][ni], STP, wmma::mem_row_major);
    __syncthreads();

    #pragma unroll
    for (int i = 0; i < 8; i++) {
        int c = tid + i * 256;
        int r = c >> 4, cc = c & 15;
        const float* sp = stage + r * STP + cc * 8;
        float4 f0 = *(const float4*)(sp);
        float4 f1 = *(const float4*)(sp + 4);
        __half2 h0 = __floats2half2_rn(f0.x, f0.y);
        __half2 h1 = __floats2half2_rn(f0.z, f0.w);
        __half2 h2 = __floats2half2_rn(f1.x, f1.y);
        __half2 h3 = __floats2half2_rn(f1.z, f1.w);
        uint4 o;
        o.x = *(uint32_t*)&h0; o.y = *(uint32_t*)&h1;
        o.z = *(uint32_t*)&h2; o.w = *(uint32_t*)&h3;
        *(uint4*)(C + (rowBase + r) * D + cc * 8) = o;
    }
}

// ---------------- fused aggregation + residual + ReLU + L2-normalize + fp16 emit ----------------
// flat edge loop, unroll-2, fp32 acc (R10 semantics). 32-bit index math + launch_bounds(256,8)
// to maximize resident warps (agg is gather-latency-bound; R15 showed strong warp sensitivity).
__global__ __launch_bounds__(256, 8) void agg_kernel(const float* __restrict__ x,
                                                     float* __restrict__ out,
                                                     const float* __restrict__ nu,
                                                     int t, int N) {
    int gw = (blockIdx.x * blockDim.x + threadIdx.x) >> 5;
    int lane = threadIdx.x & 31;
    if (gw >= N) return;
    int lane4 = lane * 4;

    const float* hin = (t == 0) ? x : g_hist[t - 1];
    float* hout = (t == 3) ? out : g_hist[t];

    float nuv[4];
    #pragma unroll
    for (int k = 0; k < 4; k++) nuv[k] = nu[k * 4 + t];

    int eBeg = g_rowStart[gw] + g_blockSums[gw >> 10];
    int cnt = 0;
    #pragma unroll
    for (int h = 0; h < 4; h++) if (h <= t) cnt += g_degD[h * N + gw];
    int eEnd = eBeg + cnt;

    float4 acc0 = make_float4(0.f, 0.f, 0.f, 0.f);
    float4 acc1 = make_float4(0.f, 0.f, 0.f, 0.f);
    int e = eBeg;
    for (; e + 2 <= eEnd; e += 2) {
        int2 p0 = g_sortedE[e];
        int2 p1 = g_sortedE[e + 1];
        int k0 = p0.x >> 20, k1 = p1.x >> 20;
        uint2 hv0 = *(const uint2*)(g_Hh[k0 - 1] + (p0.x & 0xFFFFF) * D + lane4);
        uint2 hv1 = *(const uint2*)(g_Hh[k1 - 1] + (p1.x & 0xFFFFF) * D + lane4);
        float s0 = __int_as_float(p0.y) * nuv[k0 - 1];
        float s1 = __int_as_float(p1.y) * nuv[k1 - 1];
        float2 f01 = __half22float2(*(__half2*)&hv0.x);
        float2 f23 = __half22float2(*(__half2*)&hv0.y);
        float2 g01 = __half22float2(*(__half2*)&hv1.x);
        float2 g23 = __half22float2(*(__half2*)&hv1.y);
        acc0.x = fmaf(s0, f01.x, acc0.x); acc0.y = fmaf(s0, f01.y, acc0.y);
        acc0.z = fmaf(s0, f23.x, acc0.z); acc0.w = fmaf(s0, f23.y, acc0.w);
        acc1.x = fmaf(s1, g01.x, acc1.x); acc1.y = fmaf(s1, g01.y, acc1.y);
        acc1.z = fmaf(s1, g23.x, acc1.z); acc1.w = fmaf(s1, g23.y, acc1.w);
    }
    if (e < eEnd) {
        int2 p0 = g_sortedE[e];
        int k0 = p0.x >> 20;
        uint2 hv0 = *(const uint2*)(g_Hh[k0 - 1] + (p0.x & 0xFFFFF) * D + lane4);
        float s0 = __int_as_float(p0.y) * nuv[k0 - 1];
        float2 f01 = __half22float2(*(__half2*)&hv0.x);
        float2 f23 = __half22float2(*(__half2*)&hv0.y);
        acc0.x = fmaf(s0, f01.x, acc0.x); acc0.y = fmaf(s0, f01.y, acc0.y);
        acc0.z = fmaf(s0, f23.x, acc0.z); acc0.w = fmaf(s0, f23.y, acc0.w);
    }
    float4 acc;
    acc.x = acc0.x + acc1.x; acc.y = acc0.y + acc1.y;
    acc.z = acc0.z + acc1.z; acc.w = acc0.w + acc1.w;

    int noff = gw * D + lane4;
    float4 xin = *(const float4*)(hin + noff);
    float4 v;
    v.x = xin.x + fmaxf(acc.x, 0.f);
    v.y = xin.y + fmaxf(acc.y, 0.f);
    v.z = xin.z + fmaxf(acc.z, 0.f);
    v.w = xin.w + fmaxf(acc.w, 0.f);

    float ss = v.x * v.x + v.y * v.y + v.z * v.z + v.w * v.w;
    #pragma unroll
    for (int o = 16; o; o >>= 1) ss += __shfl_xor_sync(0xffffffffu, ss, o);
    float inv = 1.0f / fmaxf(sqrtf(ss), 1e-12f);
    v.x *= inv; v.y *= inv; v.z *= inv; v.w *= inv;

    *(float4*)(hout + noff) = v;

    if (t < 3) {   // fp16 copy for next layer's GEMM A
        __half2 h0 = __floats2half2_rn(v.x, v.y);
        __half2 h1 = __floats2half2_rn(v.z, v.w);
        uint2 o;
        o.x = *(uint32_t*)&h0; o.y = *(uint32_t*)&h1;
        *(uint2*)(g_histF[t] + noff) = o;
    }
}

// ---------------- launch ----------------
extern "C" void kernel_launch(void* const* d_in, const int* in_sizes, int n_in,
                              void* d_out, int out_size) {
    const float* x    = (const float*)d_in[0];
    const int*   ei   = (const int*)d_in[1];   // [2,E]: src then dst
    const int*   attr = (const int*)d_in[2];
    const float* W    = (const float*)d_in[3]; // [4,128,128]
    const float* nu   = (const float*)d_in[4]; // [4,4]

    int N = in_sizes[0] / D;
    int E = in_sizes[2];

    cudaFuncSetAttribute(gemm_wmma_kernel, cudaFuncAttributeMaxDynamicSharedMemorySize,
                         GEMM_SMEM);

    const int thr = 256;
    int gx = (N + 127) / 128;
    int aggBlocks = (N * 32 + thr - 1) / thr;

    conv_kernel<<<(N * D + thr - 1) / thr, thr>>>(x, W, N * D);
    zero_kernel<<<(4 * N + thr - 1) / thr, thr>>>(N);
    gemm_wmma_kernel<<<dim3(gx, 1), 256, GEMM_SMEM>>>(0);   // JIT: layer-0 product
    hist_kernel<<<(E + thr - 1) / thr, thr>>>(ei, attr, N, E);
    int nb = (N + 1023) / 1024;
    scan1_kernel<<<nb, 1024>>>(N);
    scan2_kernel<<<1, 128>>>(nb);
    scatter_kernel<<<(E + thr - 1) / thr, thr>>>(ei, attr, N, E);

    agg_kernel<<<aggBlocks, thr>>>(x, (float*)d_out, nu, 0, N);
    for (int t = 1; t < 4; t++) {
        gemm_wmma_kernel<<<dim3(gx, t + 1), 256, GEMM_SMEM>>>(t);   // JIT per layer
        agg_kernel<<<aggBlocks, thr>>>(x, (float*)d_out, nu, t, N);
    }
}